// round 1
// baseline (speedup 1.0000x reference)
#include <cuda_runtime.h>
#include <cuda_bf16.h>

// Problem constants (fixed shapes for this benchmark)
#define KB    64      // boxes
#define HH    512
#define WW    512
#define NPIX  (HH*WW)

__device__ double g_sums[2];

__global__ void lz_init_kernel() {
    g_sums[0] = 0.0;
    g_sums[1] = 0.0;
}

__global__ __launch_bounds__(256) void lz_loss_kernel(
    const float* __restrict__ cm,      // center_maps, batch 0 = first 262144 floats
    const float* __restrict__ smap,    // scale_maps,  batch 0
    const float* __restrict__ ann,     // annotations, batch 0 = first 64*4 floats
    const void*  __restrict__ stridep) // stride (int32 or float32 scalar)
{
    __shared__ int   s_x1[KB], s_y1[KB], s_x2[KB], s_y2[KB], s_cx[KB], s_cy[KB];
    __shared__ float s_a[KB], s_b[KB], s_c[KB], s_lh[KB];
    __shared__ float r_c[8], r_s[8];

    const int tid = threadIdx.x;

    if (tid < KB) {
        // robust stride decode (int32 small value, else reinterpret as float)
        float stridef = 4.0f;
        if (stridep) {
            int iv = ((const int*)stridep)[0];
            if (iv > 0 && iv <= 65536) stridef = (float)iv;
            else                       stridef = __int_as_float(iv);
        }
        float inv = 1.0f / stridef;
        float4 ab = ((const float4*)ann)[tid];
        int x1 = (int)floorf(ab.x * inv);
        int y1 = (int)floorf(ab.y * inv);
        int x2 = (int)floorf(ab.z * inv);
        int y2 = (int)floorf(ab.w * inv);
        int cx = (x1 + x2) >> 1;   // nonnegative -> floor div
        int cy = (y1 + y2) >> 1;
        s_x1[tid] = x1; s_y1[tid] = y1; s_x2[tid] = x2; s_y2[tid] = y2;
        s_cx[tid] = cx; s_cy[tid] = cy;
        s_a[tid] = (float)(x1 + cx);
        s_b[tid] = (float)(y1 + cy);
        float R = sqrtf((float)cx * (float)cx + (float)cy * (float)cy);
        s_c[tid] = -0.5f / R;
        s_lh[tid] = logf((float)(y2 - y1));
    }
    __syncthreads();

    // one thread handles 4 consecutive x pixels
    const int g  = blockIdx.x * blockDim.x + tid;   // 0..65535
    const int y  = g >> 7;                          // /128
    const int x0 = (g & 127) << 2;
    const float fy = (float)y;

    float gmax[4] = {0.f, 0.f, 0.f, 0.f};
    float blog[4] = {0.f, 0.f, 0.f, 0.f};
    int   maxj[4] = {-1, -1, -1, -1};
    int   posm = 0, cenm = 0;

    #pragma unroll 4
    for (int k = 0; k < KB; k++) {
        const int cy = s_cy[k];
        const int dyo = y - cy;

        // scale-scatter / center checks (rare): x - cx == dyo, |dyo| <= 2
        if ((unsigned)(dyo + 2) <= 4u) {
            const int cx = s_cx[k];
            const int t = cx + dyo - x0;      // matching x within our 4-pixel group
            if ((unsigned)t <= 3u) {
                const int j = (dyo + 2) * KB + k;   // flattened scatter order
                if (j > maxj[t]) { maxj[t] = j; blog[t] = s_lh[k]; }
                if (dyo == 0) cenm |= (1 << t);
            }
        }

        // in-box gaussian (y gate prunes ~90%)
        if (y >= s_y1[k] && y < s_y2[k]) {
            const int x1 = s_x1[k], x2 = s_x2[k];
            const float a = s_a[k], b = s_b[k], c = s_c[k];
            const float dy = fy - b;
            const float dy2 = dy * dy;
            #pragma unroll
            for (int i = 0; i < 4; i++) {
                const int x = x0 + i;
                if (x >= x1 && x < x2) {
                    posm |= (1 << i);
                    const float dx = (float)x - a;
                    const float d = sqrtf(dx * dx + dy2);
                    const float gk = expf(c * d);
                    gmax[i] = fmaxf(gmax[i], gk);
                }
            }
        }
    }

    const float4 cm4 = ((const float4*)cm)[g];
    const float p4[4] = {cm4.x, cm4.y, cm4.z, cm4.w};

    float csum = 0.f, ssum = 0.f;
    #pragma unroll
    for (int i = 0; i < 4; i++) {
        const float p = fminf(fmaxf(p4[i], 1e-4f), 0.9999f);
        if (cenm & (1 << i)) {
            const float q = 1.0f - p;
            csum += q * q * (-logf(p));                 // ALPHA=1, GAMMA=2
        } else if (posm & (1 << i)) {
            float q = 1.0f - gmax[i];
            float w = q * q; w = w * w;                 // BETA=4
            csum += w * p * p * (-logf(1.0f - p));
        }
        if (maxj[i] >= 0) {
            const float s = smap[(size_t)g * 4 + i];
            const float d = fabsf(blog[i] - s);
            ssum += (d <= 1.0f) ? 0.5f * d * d : (d - 0.5f);
        }
    }

    // warp reduce
    #pragma unroll
    for (int off = 16; off; off >>= 1) {
        csum += __shfl_down_sync(0xffffffffu, csum, off);
        ssum += __shfl_down_sync(0xffffffffu, ssum, off);
    }
    const int lane = tid & 31;
    const int wid  = tid >> 5;
    if (lane == 0) { r_c[wid] = csum; r_s[wid] = ssum; }
    __syncthreads();
    if (tid < 8) {
        csum = r_c[tid];
        ssum = r_s[tid];
        #pragma unroll
        for (int off = 4; off; off >>= 1) {
            csum += __shfl_down_sync(0x000000ffu, csum, off);
            ssum += __shfl_down_sync(0x000000ffu, ssum, off);
        }
        if (tid == 0) {
            atomicAdd(&g_sums[0], (double)csum);
            atomicAdd(&g_sums[1], (double)ssum);
        }
    }
}

__global__ void lz_fin_kernel(float* __restrict__ out) {
    out[0] = (float)(g_sums[0] / 64.0);
    out[1] = (float)(g_sums[1] / 64.0);
}

extern "C" void kernel_launch(void* const* d_in, const int* in_sizes, int n_in,
                              void* d_out, int out_size) {
    const float* cm   = (const float*)d_in[0];
    const float* sm   = (const float*)d_in[1];
    const float* ann  = (const float*)d_in[2];
    const void*  strp = (n_in > 3) ? d_in[3] : nullptr;
    float* out = (float*)d_out;

    lz_init_kernel<<<1, 1>>>();
    lz_loss_kernel<<<NPIX / 4 / 256, 256>>>(cm, sm, ann, strp);
    lz_fin_kernel<<<1, 1>>>(out);
}

// round 2
// speedup vs baseline: 1.4706x; 1.4706x over previous
#include <cuda_runtime.h>
#include <cuda_bf16.h>

#define KB    64      // boxes
#define GRID  256     // blocks: each covers 2 rows of 512
#define TPB   256

__device__ float2       g_part[GRID];
__device__ unsigned int g_cnt;   // zero at load; wraps back to 0 every run (deterministic)

__device__ __forceinline__ float sqrt_approx(float x) {
    float r; asm("sqrt.approx.f32 %0, %1;" : "=f"(r) : "f"(x)); return r;
}

__global__ __launch_bounds__(TPB) void lz_fused_kernel(
    const float* __restrict__ cm,      // center_maps (batch 0 = first 262144)
    const float* __restrict__ smap,    // scale_maps (batch 0)
    const float* __restrict__ ann,     // annotations (batch 0 = 64 float4)
    const void*  __restrict__ stridep, // stride scalar (int32 or float32)
    float* __restrict__ out)
{
    __shared__ int   wc_g[2], wc_s[2];
    __shared__ int   n_g, n_s, s_last;
    __shared__ int   gx1[KB], gx2[KB], gy1[KB], gy2[KB];
    __shared__ float gA[KB], gB[KB], gC[KB];
    __shared__ int   scx[KB], scy[KB], skk[KB];
    __shared__ float slh[KB];
    __shared__ float r_c[8], r_s[8];

    const int tid = threadIdx.x;
    const int y0  = blockIdx.x * 2;

    // ---- phase A: per-box fields + predicates (threads 0..63, 2 full warps) ----
    int x1=0,y1=0,x2=0,y2=0,cx=0,cy=0; float A=0,B=0,C=0,LH=0;
    bool pg=false, ps=false; unsigned mg=0, ms=0;
    if (tid < KB) {
        float stridef = 4.0f;
        if (stridep) {
            int iv = ((const int*)stridep)[0];
            stridef = (iv > 0 && iv <= 65536) ? (float)iv : __int_as_float(iv);
        }
        float inv = 1.0f / stridef;
        float4 ab = ((const float4*)ann)[tid];
        x1 = (int)floorf(ab.x * inv);  y1 = (int)floorf(ab.y * inv);
        x2 = (int)floorf(ab.z * inv);  y2 = (int)floorf(ab.w * inv);
        cx = (x1 + x2) >> 1;  cy = (y1 + y2) >> 1;
        A = (float)(x1 + cx);  B = (float)(y1 + cy);
        C = -0.5f / sqrtf((float)cx*(float)cx + (float)cy*(float)cy);
        LH = __logf((float)(y2 - y1));
        pg = (y1 <= y0 + 1) && (y2 > y0);          // box touches rows {y0, y0+1}
        ps = (cy >= y0 - 2) && (cy <= y0 + 3);     // scatter diagonal touches rows
        mg = __ballot_sync(0xffffffffu, pg);
        ms = __ballot_sync(0xffffffffu, ps);
        if ((tid & 31) == 0) { wc_g[tid>>5] = __popc(mg); wc_s[tid>>5] = __popc(ms); }
    }
    __syncthreads();
    // ---- phase B: deterministic order-preserving compaction ----
    if (tid < KB) {
        const int wid = tid >> 5;
        const unsigned lt = (1u << (tid & 31)) - 1u;
        const int og = (wid ? wc_g[0] : 0) + __popc(mg & lt);
        const int os = (wid ? wc_s[0] : 0) + __popc(ms & lt);
        if (pg) { gx1[og]=x1; gx2[og]=x2; gy1[og]=y1; gy2[og]=y2; gA[og]=A; gB[og]=B; gC[og]=C; }
        if (ps) { scx[os]=cx; scy[os]=cy; skk[os]=tid; slh[os]=LH; }
        if (tid == 0) { n_g = wc_g[0]+wc_g[1]; n_s = wc_s[0]+wc_s[1]; }
    }
    __syncthreads();

    // ---- main pass: each thread = 4 consecutive x pixels of one row ----
    const int gq = blockIdx.x * TPB + tid;     // float4 index into maps
    const int y  = y0 + (tid >> 7);
    const int x0 = (tid & 127) << 2;
    const float fy = (float)y;

    float gmax[4] = {0.f,0.f,0.f,0.f};
    float blog[4] = {0.f,0.f,0.f,0.f};
    int   maxj[4] = {-1,-1,-1,-1};
    int   posm = 0, cenm = 0;

    const int ng = n_g, ns = n_s;
    for (int k = 0; k < ng; k++) {
        if (y < gy1[k] || y >= gy2[k]) continue;
        const int bx1 = gx1[k], bx2 = gx2[k];
        if (x0 + 3 < bx1 || x0 >= bx2) continue;
        const float a = gA[k], b = gB[k], c = gC[k];
        const float dy = fy - b, dy2 = dy * dy;
        #pragma unroll
        for (int i = 0; i < 4; i++) {
            const int x = x0 + i;
            if (x >= bx1 && x < bx2) {
                posm |= (1 << i);
                const float dx = (float)x - a;
                const float d  = sqrt_approx(fmaf(dx, dx, dy2));
                gmax[i] = fmaxf(gmax[i], __expf(c * d));
            }
        }
    }
    for (int k = 0; k < ns; k++) {
        const int dyo = y - scy[k];
        if ((unsigned)(dyo + 2) > 4u) continue;
        const int t = scx[k] + dyo - x0;
        if ((unsigned)t > 3u) continue;
        const int j = (dyo + 2) * KB + skk[k];   // flattened scatter index (last-write wins)
        if (j > maxj[t]) { maxj[t] = j; blog[t] = slh[k]; }
        if (dyo == 0) cenm |= (1 << t);
    }

    // ---- per-pixel loss terms ----
    const float4 cm4 = ((const float4*)cm)[gq];
    const float pv[4] = {cm4.x, cm4.y, cm4.z, cm4.w};
    float csum = 0.f, ssum = 0.f;
    #pragma unroll
    for (int i = 0; i < 4; i++) {
        const float p = fminf(fmaxf(pv[i], 1e-4f), 0.9999f);
        if (cenm & (1 << i)) {
            const float q = 1.0f - p;
            csum += q * q * (-__logf(p));                    // ALPHA=1, GAMMA=2
        } else if (posm & (1 << i)) {
            float q = 1.0f - gmax[i];
            float w = q * q; w = w * w;                      // BETA=4
            csum += w * p * p * (-__logf(1.0f - p));
        }
        if (maxj[i] >= 0) {
            const float d = fabsf(blog[i] - smap[(size_t)gq * 4 + i]);
            ssum += (d <= 1.0f) ? 0.5f * d * d : (d - 0.5f);
        }
    }

    // ---- block reduce ----
    #pragma unroll
    for (int off = 16; off; off >>= 1) {
        csum += __shfl_down_sync(0xffffffffu, csum, off);
        ssum += __shfl_down_sync(0xffffffffu, ssum, off);
    }
    if ((tid & 31) == 0) { r_c[tid>>5] = csum; r_s[tid>>5] = ssum; }
    __syncthreads();
    if (tid < 8) {
        csum = r_c[tid]; ssum = r_s[tid];
        #pragma unroll
        for (int off = 4; off; off >>= 1) {
            csum += __shfl_down_sync(0x000000ffu, csum, off);
            ssum += __shfl_down_sync(0x000000ffu, ssum, off);
        }
    }
    if (tid == 0) {
        g_part[blockIdx.x] = make_float2(csum, ssum);
        __threadfence();
        unsigned old = atomicInc(&g_cnt, GRID - 1);   // wraps to 0 -> self-resetting
        s_last = (old == GRID - 1);
    }
    __syncthreads();

    // ---- last block finalizes ----
    if (s_last) {
        volatile float* vp = (volatile float*)g_part;
        float c2 = vp[tid * 2];
        float s2 = vp[tid * 2 + 1];
        #pragma unroll
        for (int off = 16; off; off >>= 1) {
            c2 += __shfl_down_sync(0xffffffffu, c2, off);
            s2 += __shfl_down_sync(0xffffffffu, s2, off);
        }
        if ((tid & 31) == 0) { r_c[tid>>5] = c2; r_s[tid>>5] = s2; }
        __syncthreads();
        if (tid < 8) {
            c2 = r_c[tid]; s2 = r_s[tid];
            #pragma unroll
            for (int off = 4; off; off >>= 1) {
                c2 += __shfl_down_sync(0x000000ffu, c2, off);
                s2 += __shfl_down_sync(0x000000ffu, s2, off);
            }
            if (tid == 0) {
                out[0] = c2 * (1.0f / 64.0f);
                out[1] = s2 * (1.0f / 64.0f);
            }
        }
    }
}

extern "C" void kernel_launch(void* const* d_in, const int* in_sizes, int n_in,
                              void* d_out, int out_size) {
    const float* cm   = (const float*)d_in[0];
    const float* sm   = (const float*)d_in[1];
    const float* ann  = (const float*)d_in[2];
    const void*  strp = (n_in > 3) ? d_in[3] : nullptr;
    float* out = (float*)d_out;

    lz_fused_kernel<<<GRID, TPB>>>(cm, sm, ann, strp, out);
}

// round 3
// speedup vs baseline: 1.4815x; 1.0074x over previous
#include <cuda_runtime.h>
#include <cuda_bf16.h>

#define KB    64      // boxes
#define GRID  128     // one wave on 148 SMs; each block covers 4 rows of 512
#define TPB   512

__device__ float2       g_part[GRID];
__device__ unsigned int g_cnt;   // zero at load; wraps back to 0 every run (deterministic)

__device__ __forceinline__ float sqrt_approx(float x) {
    float r; asm("sqrt.approx.f32 %0, %1;" : "=f"(r) : "f"(x)); return r;
}

__global__ __launch_bounds__(TPB) void lz_fused_kernel(
    const float* __restrict__ cm,      // center_maps (batch 0 = first 262144)
    const float* __restrict__ smap,    // scale_maps (batch 0)
    const float* __restrict__ ann,     // annotations (batch 0 = 64 float4)
    const void*  __restrict__ stridep, // stride scalar (int32 or float32)
    float* __restrict__ out)
{
    __shared__ int   wc_g[2], wc_s[2];
    __shared__ int   n_g, n_s, s_last;
    __shared__ int   gx1[KB], gx2[KB], gy1[KB], gy2[KB];
    __shared__ float gA[KB], gB[KB], gC[KB];
    __shared__ int   scx[KB], scy[KB], skk[KB];
    __shared__ float slh[KB];
    __shared__ float r_c[16], r_s[16];

    const int tid = threadIdx.x;
    const int y0  = blockIdx.x * 4;

    // ---- hoisted map load: overlap DRAM latency with the whole preamble ----
    const int gq = blockIdx.x * TPB + tid;     // float4 index into maps
    const float4 cm4 = ((const float4*)cm)[gq];

    // ---- phase A: per-box fields + predicates (threads 0..63, 2 full warps) ----
    int x1=0,y1=0,x2=0,y2=0,cx=0,cy=0; float A=0,B=0,C=0,LH=0;
    bool pg=false, ps=false; unsigned mg=0, ms=0;
    if (tid < KB) {
        float stridef = 4.0f;
        if (stridep) {
            int iv = ((const int*)stridep)[0];
            stridef = (iv > 0 && iv <= 65536) ? (float)iv : __int_as_float(iv);
        }
        float inv = 1.0f / stridef;
        float4 ab = ((const float4*)ann)[tid];
        x1 = (int)floorf(ab.x * inv);  y1 = (int)floorf(ab.y * inv);
        x2 = (int)floorf(ab.z * inv);  y2 = (int)floorf(ab.w * inv);
        cx = (x1 + x2) >> 1;  cy = (y1 + y2) >> 1;
        A = (float)(x1 + cx);  B = (float)(y1 + cy);
        C = -0.5f / sqrtf((float)cx*(float)cx + (float)cy*(float)cy);
        LH = __logf((float)(y2 - y1));
        pg = (y1 <= y0 + 3) && (y2 > y0);          // box touches rows {y0..y0+3}
        ps = (cy >= y0 - 2) && (cy <= y0 + 5);     // scatter diagonal touches rows
        mg = __ballot_sync(0xffffffffu, pg);
        ms = __ballot_sync(0xffffffffu, ps);
        if ((tid & 31) == 0) { wc_g[tid>>5] = __popc(mg); wc_s[tid>>5] = __popc(ms); }
    }
    __syncthreads();
    // ---- phase B: deterministic order-preserving compaction ----
    if (tid < KB) {
        const int wid = tid >> 5;
        const unsigned lt = (1u << (tid & 31)) - 1u;
        const int og = (wid ? wc_g[0] : 0) + __popc(mg & lt);
        const int os = (wid ? wc_s[0] : 0) + __popc(ms & lt);
        if (pg) { gx1[og]=x1; gx2[og]=x2; gy1[og]=y1; gy2[og]=y2; gA[og]=A; gB[og]=B; gC[og]=C; }
        if (ps) { scx[os]=cx; scy[os]=cy; skk[os]=tid; slh[os]=LH; }
        if (tid == 0) { n_g = wc_g[0]+wc_g[1]; n_s = wc_s[0]+wc_s[1]; }
    }
    __syncthreads();

    // ---- main pass: each thread = 4 consecutive x pixels of one row ----
    const int y  = y0 + (tid >> 7);
    const int x0 = (tid & 127) << 2;
    const float fy = (float)y;

    float gmax[4] = {0.f,0.f,0.f,0.f};
    float blog[4] = {0.f,0.f,0.f,0.f};
    int   maxj[4] = {-1,-1,-1,-1};
    int   posm = 0, cenm = 0;

    const int ng = n_g, ns = n_s;
    for (int k = 0; k < ng; k++) {
        if (y < gy1[k] || y >= gy2[k]) continue;
        const int bx1 = gx1[k], bx2 = gx2[k];
        if (x0 + 3 < bx1 || x0 >= bx2) continue;
        const float a = gA[k], b = gB[k], c = gC[k];
        const float dy = fy - b, dy2 = dy * dy;
        #pragma unroll
        for (int i = 0; i < 4; i++) {
            const int x = x0 + i;
            if (x >= bx1 && x < bx2) {
                posm |= (1 << i);
                const float dx = (float)x - a;
                const float d  = sqrt_approx(fmaf(dx, dx, dy2));
                gmax[i] = fmaxf(gmax[i], __expf(c * d));
            }
        }
    }
    for (int k = 0; k < ns; k++) {
        const int dyo = y - scy[k];
        if ((unsigned)(dyo + 2) > 4u) continue;
        const int t = scx[k] + dyo - x0;
        if ((unsigned)t > 3u) continue;
        const int j = (dyo + 2) * KB + skk[k];   // flattened scatter index (last-write wins)
        if (j > maxj[t]) { maxj[t] = j; blog[t] = slh[k]; }
        if (dyo == 0) cenm |= (1 << t);
    }

    // ---- per-pixel loss terms ----
    const float pv[4] = {cm4.x, cm4.y, cm4.z, cm4.w};
    float csum = 0.f, ssum = 0.f;
    #pragma unroll
    for (int i = 0; i < 4; i++) {
        const float p = fminf(fmaxf(pv[i], 1e-4f), 0.9999f);
        if (cenm & (1 << i)) {
            const float q = 1.0f - p;
            csum += q * q * (-__logf(p));                    // ALPHA=1, GAMMA=2
        } else if (posm & (1 << i)) {
            float q = 1.0f - gmax[i];
            float w = q * q; w = w * w;                      // BETA=4
            csum += w * p * p * (-__logf(1.0f - p));
        }
        if (maxj[i] >= 0) {
            const float d = fabsf(blog[i] - smap[(size_t)gq * 4 + i]);
            ssum += (d <= 1.0f) ? 0.5f * d * d : (d - 0.5f);
        }
    }

    // ---- block reduce (16 warps) ----
    #pragma unroll
    for (int off = 16; off; off >>= 1) {
        csum += __shfl_down_sync(0xffffffffu, csum, off);
        ssum += __shfl_down_sync(0xffffffffu, ssum, off);
    }
    if ((tid & 31) == 0) { r_c[tid>>5] = csum; r_s[tid>>5] = ssum; }
    __syncthreads();
    if (tid < 16) {
        csum = r_c[tid]; ssum = r_s[tid];
        #pragma unroll
        for (int off = 8; off; off >>= 1) {
            csum += __shfl_down_sync(0x0000ffffu, csum, off);
            ssum += __shfl_down_sync(0x0000ffffu, ssum, off);
        }
    }
    if (tid == 0) {
        g_part[blockIdx.x] = make_float2(csum, ssum);
        __threadfence();
        unsigned old = atomicInc(&g_cnt, GRID - 1);   // wraps to 0 -> self-resetting
        s_last = (old == GRID - 1);
    }
    __syncthreads();

    // ---- last block finalizes (128 partials, first 4 warps) ----
    if (s_last) {
        float c2 = 0.f, s2 = 0.f;
        if (tid < GRID) {
            volatile float* vp = (volatile float*)g_part;
            c2 = vp[tid * 2];
            s2 = vp[tid * 2 + 1];
        }
        #pragma unroll
        for (int off = 16; off; off >>= 1) {
            c2 += __shfl_down_sync(0xffffffffu, c2, off);
            s2 += __shfl_down_sync(0xffffffffu, s2, off);
        }
        if ((tid & 31) == 0 && tid < GRID) { r_c[tid>>5] = c2; r_s[tid>>5] = s2; }
        __syncthreads();
        if (tid < 4) {
            c2 = r_c[tid]; s2 = r_s[tid];
            #pragma unroll
            for (int off = 2; off; off >>= 1) {
                c2 += __shfl_down_sync(0x0000000fu, c2, off);
                s2 += __shfl_down_sync(0x0000000fu, s2, off);
            }
            if (tid == 0) {
                out[0] = c2 * (1.0f / 64.0f);
                out[1] = s2 * (1.0f / 64.0f);
            }
        }
    }
}

extern "C" void kernel_launch(void* const* d_in, const int* in_sizes, int n_in,
                              void* d_out, int out_size) {
    const float* cm   = (const float*)d_in[0];
    const float* sm   = (const float*)d_in[1];
    const float* ann  = (const float*)d_in[2];
    const void*  strp = (n_in > 3) ? d_in[3] : nullptr;
    float* out = (float*)d_out;

    lz_fused_kernel<<<GRID, TPB>>>(cm, sm, ann, strp, out);
}

// round 4
// speedup vs baseline: 1.7857x; 1.2054x over previous
#include <cuda_runtime.h>
#include <cuda_bf16.h>

#define KB    64      // boxes
#define GRID  128     // block b handles striped rows {b, b+128, b+256, b+384}
#define TPB   512

__device__ float2       g_part[GRID];
__device__ unsigned int g_cnt;   // zero at load; wraps back to 0 every run (deterministic)

__device__ __forceinline__ float sqrt_approx(float x) {
    float r; asm("sqrt.approx.f32 %0, %1;" : "=f"(r) : "f"(x)); return r;
}

__global__ __launch_bounds__(TPB) void lz_fused_kernel(
    const float* __restrict__ cm,      // center_maps (batch 0 = first 262144)
    const float* __restrict__ smap,    // scale_maps (batch 0)
    const float* __restrict__ ann,     // annotations (batch 0 = 64 float4)
    const void*  __restrict__ stridep, // stride scalar (int32 or float32)
    float* __restrict__ out)
{
    __shared__ float4 Lg[4][KB];      // per-row box record {fx1, fx2, A, C}
    __shared__ float  Ldy2[4][KB];    // per-row precomputed dy^2
    __shared__ float  Scol[4][KB];    // per-row scatter column
    __shared__ int    Sj[4][KB];      // flattened scatter index
    __shared__ float  Slh[4][KB];     // log(height)
    __shared__ int    cg[4][2], cs[4][2], ng[4], ns[4];
    __shared__ float  r_c[16], r_s[16];
    __shared__ int    s_last;

    const int tid = threadIdx.x;
    const int b   = blockIdx.x;

    // ---- hoisted map load: overlap DRAM latency with the whole preamble ----
    const int rmain = tid >> 7;          // which of the 4 striped rows
    const int cgrp  = tid & 127;         // float4 column group
    const int y     = b + (rmain << 7);  // striped row
    const int gq    = y * 128 + cgrp;    // float4 index into maps
    const float4 cm4 = ((const float4*)cm)[gq];

    // ---- phase A: 256 threads = (4 rows) x (64 boxes): predicates + ballots ----
    int rr = 0, k = 0;
    int x1 = 0, y1 = 0, x2 = 0, y2 = 0, cx = 0, cy = 0;
    float A = 0.f, B = 0.f, C = 0.f, LH = 0.f;
    bool pg = false, ps = false;
    unsigned mg = 0, ms = 0;
    if (tid < 256) {
        rr = tid >> 6;  k = tid & 63;
        const int yr = b + (rr << 7);
        float stridef = 4.0f;
        if (stridep) {
            int iv = ((const int*)stridep)[0];
            stridef = (iv > 0 && iv <= 65536) ? (float)iv : __int_as_float(iv);
        }
        const float inv = 1.0f / stridef;
        const float4 ab = ((const float4*)ann)[k];
        x1 = (int)floorf(ab.x * inv);  y1 = (int)floorf(ab.y * inv);
        x2 = (int)floorf(ab.z * inv);  y2 = (int)floorf(ab.w * inv);
        cx = (x1 + x2) >> 1;  cy = (y1 + y2) >> 1;
        A = (float)(x1 + cx);  B = (float)(y1 + cy);
        C = -0.5f / sqrtf((float)cx*(float)cx + (float)cy*(float)cy);
        LH = __logf((float)(y2 - y1));
        pg = (yr >= y1) && (yr < y2);                 // this row intersects box
        ps = ((unsigned)(yr - cy + 2)) <= 4u;         // scatter diagonal hits row
        mg = __ballot_sync(0xffffffffu, pg);
        ms = __ballot_sync(0xffffffffu, ps);
        if ((k & 31) == 0) { cg[rr][k>>5] = __popc(mg); cs[rr][k>>5] = __popc(ms); }
    }
    __syncthreads();
    // ---- phase B: deterministic order-preserving per-row compaction ----
    if (tid < 256) {
        const unsigned lt = (1u << (k & 31)) - 1u;
        const int h  = k >> 5;
        const int og = (h ? cg[rr][0] : 0) + __popc(mg & lt);
        const int os = (h ? cs[rr][0] : 0) + __popc(ms & lt);
        const int yr = b + (rr << 7);
        if (pg) {
            Lg[rr][og] = make_float4((float)x1, (float)x2, A, C);
            const float dy = (float)yr - B;
            Ldy2[rr][og] = dy * dy;
        }
        if (ps) {
            const int dyo = yr - cy;
            Scol[rr][os] = (float)(cx + dyo);
            Sj[rr][os]   = (dyo + 2) * KB + k;   // last-write-wins order
            Slh[rr][os]  = LH;
        }
        if (k == 0) { ng[rr] = cg[rr][0] + cg[rr][1]; ns[rr] = cs[rr][0] + cs[rr][1]; }
    }
    __syncthreads();

    // ---- main pass: each thread = 4 consecutive x pixels of its striped row ----
    const int   x0  = cgrp << 2;
    const float fx0 = (float)x0;

    float gmax[4] = {0.f,0.f,0.f,0.f};
    float blog[4] = {0.f,0.f,0.f,0.f};
    int   maxj[4] = {-1,-1,-1,-1};
    int   posm = 0, cenm = 0;

    const int NG = ng[rmain], NS = ns[rmain];
    for (int kk = 0; kk < NG; kk++) {
        const float4 bd = Lg[rmain][kk];          // {fx1, fx2, A, C}
        if (fx0 + 3.0f >= bd.x && fx0 < bd.y) {
            const float dy2 = Ldy2[rmain][kk];
            #pragma unroll
            for (int i = 0; i < 4; i++) {
                const float fx = fx0 + (float)i;
                if (fx >= bd.x && fx < bd.y) {
                    posm |= (1 << i);
                    const float dx = fx - bd.z;
                    const float d  = sqrt_approx(fmaf(dx, dx, dy2));
                    gmax[i] = fmaxf(gmax[i], __expf(bd.w * d));
                }
            }
        }
    }
    for (int kk = 0; kk < NS; kk++) {
        const int t = (int)Scol[rmain][kk] - x0;
        if ((unsigned)t <= 3u) {
            const int j = Sj[rmain][kk];
            if (j > maxj[t]) { maxj[t] = j; blog[t] = Slh[rmain][kk]; }
            if (j >= 2*KB && j < 3*KB) cenm |= (1 << t);   // dyo == 0 band
        }
    }

    // ---- per-pixel loss terms ----
    const float pv[4] = {cm4.x, cm4.y, cm4.z, cm4.w};
    float csum = 0.f, ssum = 0.f;
    #pragma unroll
    for (int i = 0; i < 4; i++) {
        const float p = fminf(fmaxf(pv[i], 1e-4f), 0.9999f);
        if (cenm & (1 << i)) {
            const float q = 1.0f - p;
            csum += q * q * (-__logf(p));                    // ALPHA=1, GAMMA=2
        } else if (posm & (1 << i)) {
            float q = 1.0f - gmax[i];
            float w = q * q; w = w * w;                      // BETA=4
            csum += w * p * p * (-__logf(1.0f - p));
        }
        if (maxj[i] >= 0) {
            const float d = fabsf(blog[i] - smap[(size_t)gq * 4 + i]);
            ssum += (d <= 1.0f) ? 0.5f * d * d : (d - 0.5f);
        }
    }

    // ---- block reduce (16 warps) ----
    #pragma unroll
    for (int off = 16; off; off >>= 1) {
        csum += __shfl_down_sync(0xffffffffu, csum, off);
        ssum += __shfl_down_sync(0xffffffffu, ssum, off);
    }
    if ((tid & 31) == 0) { r_c[tid>>5] = csum; r_s[tid>>5] = ssum; }
    __syncthreads();
    if (tid < 16) {
        csum = r_c[tid]; ssum = r_s[tid];
        #pragma unroll
        for (int off = 8; off; off >>= 1) {
            csum += __shfl_down_sync(0x0000ffffu, csum, off);
            ssum += __shfl_down_sync(0x0000ffffu, ssum, off);
        }
    }
    if (tid == 0) {
        g_part[b] = make_float2(csum, ssum);
        __threadfence();
        unsigned old = atomicInc(&g_cnt, GRID - 1);   // wraps to 0 -> self-resetting
        s_last = (old == GRID - 1);
    }
    __syncthreads();

    // ---- last block finalizes (128 partials) ----
    if (s_last) {
        float c2 = 0.f, s2 = 0.f;
        if (tid < GRID) {
            volatile float* vp = (volatile float*)g_part;
            c2 = vp[tid * 2];
            s2 = vp[tid * 2 + 1];
        }
        #pragma unroll
        for (int off = 16; off; off >>= 1) {
            c2 += __shfl_down_sync(0xffffffffu, c2, off);
            s2 += __shfl_down_sync(0xffffffffu, s2, off);
        }
        if ((tid & 31) == 0 && tid < GRID) { r_c[tid>>5] = c2; r_s[tid>>5] = s2; }
        __syncthreads();
        if (tid < 4) {
            c2 = r_c[tid]; s2 = r_s[tid];
            #pragma unroll
            for (int off = 2; off; off >>= 1) {
                c2 += __shfl_down_sync(0x0000000fu, c2, off);
                s2 += __shfl_down_sync(0x0000000fu, s2, off);
            }
            if (tid == 0) {
                out[0] = c2 * (1.0f / 64.0f);
                out[1] = s2 * (1.0f / 64.0f);
            }
        }
    }
}

extern "C" void kernel_launch(void* const* d_in, const int* in_sizes, int n_in,
                              void* d_out, int out_size) {
    const float* cm   = (const float*)d_in[0];
    const float* sm   = (const float*)d_in[1];
    const float* ann  = (const float*)d_in[2];
    const void*  strp = (n_in > 3) ? d_in[3] : nullptr;
    float* out = (float*)d_out;

    lz_fused_kernel<<<GRID, TPB>>>(cm, sm, ann, strp, out);
}